// round 1
// baseline (speedup 1.0000x reference)
#include <cuda_runtime.h>
#include <cstdint>

// ---------------- problem constants ----------------
#define H 256
#define W 256
#define NA 9
#define HWPIX 65536            // H*W
#define TOT 589824             // H*W*NA
#define PRE 6000
#define POST 300
#define NMS_T 0.7f
#define NWORDS 94              // ceil(6000/64)
#define WPITCH 96
#define CAP 16384              // candidate capacity (power of 2 for bitonic)
#define NBINS 65536
#define SORT_SMEM (CAP * 8)

// ---------------- scratch (device globals; no allocation allowed) ----------------
__device__ unsigned long long g_keys[TOT];
__device__ unsigned int       g_hist[NBINS];
__device__ int                g_thr;
__device__ int                g_candcnt;
__device__ unsigned long long g_cand[CAP];
__device__ float4             g_boxes[PRE];
__device__ unsigned long long g_supp[WPITCH];
__device__ unsigned long long g_mask[(size_t)PRE * WPITCH];

// ---------------- box decode (explicit RN intrinsics: match XLA no-fma semantics) ----------------
__device__ __forceinline__ float4 decode_box(int pix, int a,
                                             const float* __restrict__ del,
                                             const float4* __restrict__ anc,
                                             float imW1, float imH1, float ms,
                                             bool& valid)
{
    float sx = __fmul_rn((float)(pix & (W - 1)), 16.0f);
    float sy = __fmul_rn((float)(pix >> 8), 16.0f);
    float4 A = anc[a];
    float ax1 = __fadd_rn(A.x, sx);
    float ay1 = __fadd_rn(A.y, sy);
    float ax2 = __fadd_rn(A.z, sx);
    float ay2 = __fadd_rn(A.w, sy);
    float aw  = __fadd_rn(__fsub_rn(ax2, ax1), 1.0f);
    float ah  = __fadd_rn(__fsub_rn(ay2, ay1), 1.0f);
    float acx = __fadd_rn(ax1, __fmul_rn(0.5f, aw));
    float acy = __fadd_rn(ay1, __fmul_rn(0.5f, ah));

    int base = (4 * a) * HWPIX + pix;
    float dx = del[base];
    float dy = del[base + HWPIX];
    float dw = del[base + 2 * HWPIX];
    float dh = del[base + 3 * HWPIX];
    dw = fminf(fmaxf(dw, -10.0f), 10.0f);
    dh = fminf(fmaxf(dh, -10.0f), 10.0f);

    float pcx = __fadd_rn(__fmul_rn(dx, aw), acx);
    float pcy = __fadd_rn(__fmul_rn(dy, ah), acy);
    float pw  = __fmul_rn(expf(dw), aw);
    float ph  = __fmul_rn(expf(dh), ah);

    float hx = __fmul_rn(0.5f, pw);
    float hy = __fmul_rn(0.5f, ph);
    float x1 = fminf(fmaxf(__fsub_rn(pcx, hx), 0.0f), imW1);
    float y1 = fminf(fmaxf(__fsub_rn(pcy, hy), 0.0f), imH1);
    float x2 = fminf(fmaxf(__fsub_rn(__fadd_rn(pcx, hx), 1.0f), 0.0f), imW1);
    float y2 = fminf(fmaxf(__fsub_rn(__fadd_rn(pcy, hy), 1.0f), 0.0f), imH1);

    valid = (__fadd_rn(__fsub_rn(x2, x1), 1.0f) >= ms) &&
            (__fadd_rn(__fsub_rn(y2, y1), 1.0f) >= ms);
    return make_float4(x1, y1, x2, y2);
}

// ---------------- K0: zero scratch ----------------
__global__ void k0_zero()
{
    int i = blockIdx.x * blockDim.x + threadIdx.x;
    if (i < NBINS)  g_hist[i] = 0u;
    if (i < WPITCH) g_supp[i] = 0ull;
    if (i == 0)     g_candcnt = 0;
}

// ---------------- K1: keys + histogram ----------------
__global__ void k1_keys(const float* __restrict__ probs,
                        const float* __restrict__ del,
                        const float* __restrict__ img,
                        const float* __restrict__ anchors)
{
    int pix = blockIdx.x * blockDim.x + threadIdx.x;
    if (pix >= HWPIX) return;
    float imH1 = __fsub_rn(img[0], 1.0f);
    float imW1 = __fsub_rn(img[1], 1.0f);
    float ms   = __fmul_rn(16.0f, img[2]);
    const float4* anc = (const float4*)anchors;

#pragma unroll
    for (int a = 0; a < NA; ++a) {
        float score = probs[(NA + a) * HWPIX + pix];
        bool valid;
        (void)decode_box(pix, a, del, anc, imW1, imH1, ms, valid);
        unsigned int idx = (unsigned int)(pix * NA + a);
        unsigned long long key = 0ull;
        if (valid) {
            unsigned int sb = __float_as_uint(score);
            unsigned int ob = (sb & 0x80000000u) ? ~sb : (sb | 0x80000000u);
            key = ((unsigned long long)ob << 32) | (unsigned long long)(0xFFFFFFFFu - idx);
            atomicAdd(&g_hist[ob >> 16], 1u);
        }
        g_keys[idx] = key;
    }
}

// ---------------- K2: radix threshold (single block) ----------------
__global__ void k2_threshold()
{
    __shared__ unsigned int csum[1024];
    int t = threadIdx.x;
    unsigned int s = 0;
    int b0 = t * 64;
    for (int b = b0; b < b0 + 64; ++b) s += g_hist[b];
    csum[t] = s;
    __syncthreads();
    if (t == 0) {
        unsigned int acc = 0;
        int c;
        for (c = 1023; c >= 0; --c) {
            if (acc + csum[c] >= (unsigned)PRE) break;
            acc += csum[c];
        }
        int T = 0;
        if (c >= 0) {
            int b;
            for (b = c * 64 + 63; b >= c * 64; --b) {
                acc += g_hist[b];
                if (acc >= (unsigned)PRE) break;
            }
            T = (b < c * 64) ? c * 64 : b;
        }
        g_thr = T;
    }
}

// ---------------- K3: compact candidates ----------------
__global__ void k3_compact()
{
    int i = blockIdx.x * blockDim.x + threadIdx.x;
    if (i >= TOT) return;
    unsigned long long key = g_keys[i];
    if (key != 0ull && (unsigned int)(key >> 48) >= (unsigned int)g_thr) {
        int pos = atomicAdd(&g_candcnt, 1);
        if (pos < CAP) g_cand[pos] = key;
    }
}

// ---------------- K4: single-block bitonic sort + decode top-6000 ----------------
__global__ void k4_sort(const float* __restrict__ del,
                        const float* __restrict__ img,
                        const float* __restrict__ anchors)
{
    extern __shared__ unsigned long long sk[];
    int tid = threadIdx.x;
    int cc = g_candcnt;
    if (cc > CAP) cc = CAP;
    for (int t = tid; t < CAP; t += blockDim.x)
        sk[t] = (t < cc) ? g_cand[t] : 0ull;
    __syncthreads();

    for (int k = 2; k <= CAP; k <<= 1) {
        for (int j = k >> 1; j > 0; j >>= 1) {
            for (int i = tid; i < CAP; i += blockDim.x) {
                int l = i ^ j;
                if (l > i) {
                    unsigned long long a = sk[i], b = sk[l];
                    bool sw = ((i & k) == 0) ? (a < b) : (a > b);   // descending
                    if (sw) { sk[i] = b; sk[l] = a; }
                }
            }
            __syncthreads();
        }
    }

    float imH1 = __fsub_rn(img[0], 1.0f);
    float imW1 = __fsub_rn(img[1], 1.0f);
    float ms   = __fmul_rn(16.0f, img[2]);
    const float4* anc = (const float4*)anchors;

    for (int t = tid; t < PRE; t += blockDim.x) {
        unsigned long long key = sk[t];
        if (key == 0ull) {
            atomicOr(&g_supp[t >> 6], 1ull << (t & 63));
            g_boxes[t] = make_float4(0.f, 0.f, 0.f, 0.f);
        } else {
            unsigned int idx = 0xFFFFFFFFu - (unsigned int)(key & 0xFFFFFFFFull);
            int pix = idx / NA;
            int a   = idx - pix * NA;
            bool valid;
            g_boxes[t] = decode_box(pix, a, del, anc, imW1, imH1, ms, valid);
        }
    }
}

// ---------------- K5: IoU bitmask matrix (94x94 blocks of 64) ----------------
__global__ void k5_mask()
{
    __shared__ float4 cb[64];
    int cB = blockIdx.x, rB = blockIdx.y;
    int t = threadIdx.x;
    int j0 = cB * 64;
    int j = j0 + t;
    cb[t] = (j < PRE) ? g_boxes[j] : make_float4(0.f, 0.f, -1.f, -1.f);
    __syncthreads();

    int i = rB * 64 + t;
    if (i >= PRE) return;

    unsigned long long word = 0ull;
    if (j0 + 63 > i) {
        float4 bi = g_boxes[i];
        float ai = __fmul_rn(__fadd_rn(__fsub_rn(bi.z, bi.x), 1.0f),
                             __fadd_rn(__fsub_rn(bi.w, bi.y), 1.0f));
        int cmax = min(64, PRE - j0);
        for (int c = 0; c < cmax; ++c) {
            int jj = j0 + c;
            if (jj <= i) continue;
            float4 bj = cb[c];
            float ix1 = fmaxf(bi.x, bj.x);
            float iy1 = fmaxf(bi.y, bj.y);
            float ix2 = fminf(bi.z, bj.z);
            float iy2 = fminf(bi.w, bj.w);
            float iw = fmaxf(__fadd_rn(__fsub_rn(ix2, ix1), 1.0f), 0.0f);
            float ih = fmaxf(__fadd_rn(__fsub_rn(iy2, iy1), 1.0f), 0.0f);
            float inter = __fmul_rn(iw, ih);
            float aj = __fmul_rn(__fadd_rn(__fsub_rn(bj.z, bj.x), 1.0f),
                                 __fadd_rn(__fsub_rn(bj.w, bj.y), 1.0f));
            float iou = __fdiv_rn(inter, __fsub_rn(__fadd_rn(ai, aj), inter));
            if (iou > NMS_T) word |= (1ull << c);
        }
    }
    g_mask[(size_t)i * WPITCH + cB] = word;
}

// ---------------- K6: sequential NMS scan (1 warp, 64 bits per broadcast, early exit @300) ----------------
__global__ void k6_scan(float* __restrict__ out)
{
    int lane = threadIdx.x;
    unsigned long long S0 = g_supp[lane];
    unsigned long long S1 = g_supp[lane + 32];
    unsigned long long S2 = (lane < 30) ? g_supp[lane + 64] : 0ull;

    int kept = 0;
    for (int wi = 0; wi < NWORDS && kept < POST; ++wi) {
        int slot = wi >> 5, src = wi & 31;
        unsigned long long mine = (slot == 0) ? S0 : ((slot == 1) ? S1 : S2);
        unsigned long long w = __shfl_sync(0xFFFFFFFFu, mine, src);
        int bmax = min(64, PRE - wi * 64);
        for (int b = 0; b < bmax; ++b) {
            if (!((w >> b) & 1ull)) {
                int i = wi * 64 + b;
                const float* bp = (const float*)&g_boxes[i];
                if (lane < 4)       out[kept * 5 + 1 + lane] = bp[lane];
                else if (lane == 4) out[kept * 5] = 0.0f;
                kept++;
                size_t base = (size_t)i * WPITCH;
                unsigned long long r0 = g_mask[base + lane];
                unsigned long long r1 = g_mask[base + lane + 32];
                unsigned long long r2 = (lane < 30) ? g_mask[base + lane + 64] : 0ull;
                S0 |= r0; S1 |= r1; S2 |= r2;
                unsigned long long rmine = (slot == 0) ? r0 : ((slot == 1) ? r1 : r2);
                w |= __shfl_sync(0xFFFFFFFFu, rmine, src);
                if (kept >= POST) break;
            }
        }
    }
    // zero-fill remaining rows
    int rem = (POST - kept) * 5;
    for (int z = lane; z < rem; z += 32)
        out[kept * 5 + z] = 0.0f;
}

// ---------------- launch ----------------
extern "C" void kernel_launch(void* const* d_in, const int* in_sizes, int n_in,
                              void* d_out, int out_size)
{
    const float* probs   = (const float*)d_in[0];
    const float* del     = (const float*)d_in[1];
    const float* img     = (const float*)d_in[2];
    const float* anchors = (const float*)d_in[3];
    float* out = (float*)d_out;

    cudaFuncSetAttribute(k4_sort, cudaFuncAttributeMaxDynamicSharedMemorySize, SORT_SMEM);

    k0_zero<<<256, 256>>>();
    k1_keys<<<HWPIX / 256, 256>>>(probs, del, img, anchors);
    k2_threshold<<<1, 1024>>>();
    k3_compact<<<TOT / 256, 256>>>();
    k4_sort<<<1, 1024, SORT_SMEM>>>(del, img, anchors);
    k5_mask<<<dim3(NWORDS, NWORDS), 64>>>();
    k6_scan<<<1, 32>>>(out);
}

// round 2
// speedup vs baseline: 1.3570x; 1.3570x over previous
#include <cuda_runtime.h>
#include <cstdint>

typedef unsigned long long u64;
typedef unsigned int u32;

// ---------------- problem constants ----------------
#define H 256
#define W 256
#define NA 9
#define HWPIX 65536            // H*W
#define TOT 589824             // H*W*NA
#define PRE 6000
#define POST 300
#define NMS_T 0.7f
#define NWORDS 94              // ceil(6000/64)
#define WPITCH 96
#define CAPBIG 16384           // staging candidate capacity
#define SORTN 8192             // sorted array (power of 2)
#define CHUNK 2048
#define NCHUNK 4
#define NBINS 65536

// ---------------- scratch ----------------
__device__ u64 g_keys[TOT];
__device__ u32 g_hist[NBINS];
__device__ u32 g_hist2[NBINS];
__device__ int g_T1;
__device__ u32 g_above;
__device__ u64 g_thr64;
__device__ int g_candcnt;
__device__ int g_cnt2;
__device__ u64 g_cand[CAPBIG];
__device__ u64 g_sort[SORTN];
__device__ float4 g_boxes[PRE];
__device__ u64 g_supp[WPITCH];
__device__ u64 g_mask[(size_t)PRE * WPITCH];

// ---------------- box decode (explicit RN: match XLA no-fma) ----------------
__device__ __forceinline__ float4 decode_box(int pix, int a,
                                             const float* __restrict__ del,
                                             const float4* __restrict__ anc,
                                             float imW1, float imH1, float ms,
                                             bool& valid)
{
    float sx = __fmul_rn((float)(pix & (W - 1)), 16.0f);
    float sy = __fmul_rn((float)(pix >> 8), 16.0f);
    float4 A = anc[a];
    float ax1 = __fadd_rn(A.x, sx);
    float ay1 = __fadd_rn(A.y, sy);
    float ax2 = __fadd_rn(A.z, sx);
    float ay2 = __fadd_rn(A.w, sy);
    float aw  = __fadd_rn(__fsub_rn(ax2, ax1), 1.0f);
    float ah  = __fadd_rn(__fsub_rn(ay2, ay1), 1.0f);
    float acx = __fadd_rn(ax1, __fmul_rn(0.5f, aw));
    float acy = __fadd_rn(ay1, __fmul_rn(0.5f, ah));

    int base = (4 * a) * HWPIX + pix;
    float dx = del[base];
    float dy = del[base + HWPIX];
    float dw = del[base + 2 * HWPIX];
    float dh = del[base + 3 * HWPIX];
    dw = fminf(fmaxf(dw, -10.0f), 10.0f);
    dh = fminf(fmaxf(dh, -10.0f), 10.0f);

    float pcx = __fadd_rn(__fmul_rn(dx, aw), acx);
    float pcy = __fadd_rn(__fmul_rn(dy, ah), acy);
    float pw  = __fmul_rn(expf(dw), aw);
    float ph  = __fmul_rn(expf(dh), ah);

    float hx = __fmul_rn(0.5f, pw);
    float hy = __fmul_rn(0.5f, ph);
    float x1 = fminf(fmaxf(__fsub_rn(pcx, hx), 0.0f), imW1);
    float y1 = fminf(fmaxf(__fsub_rn(pcy, hy), 0.0f), imH1);
    float x2 = fminf(fmaxf(__fsub_rn(__fadd_rn(pcx, hx), 1.0f), 0.0f), imW1);
    float y2 = fminf(fmaxf(__fsub_rn(__fadd_rn(pcy, hy), 1.0f), 0.0f), imH1);

    valid = (__fadd_rn(__fsub_rn(x2, x1), 1.0f) >= ms) &&
            (__fadd_rn(__fsub_rn(y2, y1), 1.0f) >= ms);
    return make_float4(x1, y1, x2, y2);
}

// ---------------- K0: zero scratch ----------------
__global__ void k0_zero()
{
    int i = blockIdx.x * blockDim.x + threadIdx.x;
    if (i < NBINS)  { g_hist[i] = 0u; g_hist2[i] = 0u; }
    if (i < SORTN)  g_sort[i] = 0ull;
    if (i < WPITCH) g_supp[i] = 0ull;
    if (i == 0)     { g_candcnt = 0; g_cnt2 = 0; }
}

// ---------------- K1: keys + level-1 histogram ----------------
__global__ void k1_keys(const float* __restrict__ probs,
                        const float* __restrict__ del,
                        const float* __restrict__ img,
                        const float* __restrict__ anchors)
{
    int pix = blockIdx.x * blockDim.x + threadIdx.x;
    if (pix >= HWPIX) return;
    float imH1 = __fsub_rn(img[0], 1.0f);
    float imW1 = __fsub_rn(img[1], 1.0f);
    float ms   = __fmul_rn(16.0f, img[2]);
    const float4* anc = (const float4*)anchors;

#pragma unroll
    for (int a = 0; a < NA; ++a) {
        float score = probs[(NA + a) * HWPIX + pix];
        bool valid;
        (void)decode_box(pix, a, del, anc, imW1, imH1, ms, valid);
        u32 idx = (u32)(pix * NA + a);
        u64 key = 0ull;
        if (valid) {
            u32 sb = __float_as_uint(score);
            u32 ob = (sb & 0x80000000u) ? ~sb : (sb | 0x80000000u);
            key = ((u64)ob << 32) | (u64)(0xFFFFFFFFu - idx);
            atomicAdd(&g_hist[ob >> 16], 1u);
        }
        g_keys[idx] = key;
    }
}

// ---------------- K2: level-1 radix threshold ----------------
__global__ void k2_t1()
{
    __shared__ u32 csum[1024];
    int t = threadIdx.x;
    u32 s = 0;
    int b0 = t * 64;
    for (int b = b0; b < b0 + 64; ++b) s += g_hist[b];
    csum[t] = s;
    __syncthreads();
    if (t == 0) {
        u32 acc = 0;
        int c;
        for (c = 1023; c >= 0; --c) {
            if (acc + csum[c] >= (u32)PRE) break;
            acc += csum[c];
        }
        if (c < 0) { g_T1 = 0; g_above = 0; return; }   // fewer than PRE valid
        int b;
        for (b = c * 64 + 63; b >= c * 64; --b) {
            acc += g_hist[b];
            if (acc >= (u32)PRE) break;
        }
        if (b < c * 64) b = c * 64;
        g_T1 = b;
        g_above = acc - g_hist[b];   // strictly above threshold bin
    }
}

// ---------------- K3: compact candidates >= T1 + level-2 histogram ----------------
__global__ void k3_compact()
{
    int i = blockIdx.x * blockDim.x + threadIdx.x;
    if (i >= TOT) return;
    u64 key = g_keys[i];
    if (key == 0ull) return;
    u32 top = (u32)(key >> 48);
    u32 T1 = (u32)g_T1;
    if (top >= T1) {
        int pos = atomicAdd(&g_candcnt, 1);
        if (pos < CAPBIG) g_cand[pos] = key;
        if (top == T1) atomicAdd(&g_hist2[(u32)(key >> 32) & 0xFFFFu], 1u);
    }
}

// ---------------- K2b: level-2 threshold -> 48-bit combined threshold ----------------
__global__ void k2b_t2()
{
    __shared__ u32 csum[1024];
    int t = threadIdx.x;
    u32 s = 0;
    int b0 = t * 64;
    for (int b = b0; b < b0 + 64; ++b) s += g_hist2[b];
    csum[t] = s;
    __syncthreads();
    if (t == 0) {
        u32 above = g_above;
        u32 T1 = (u32)g_T1;
        int need = PRE - (int)above;
        u32 acc = 0;
        int c;
        for (c = 1023; c >= 0; --c) {
            if ((int)(acc + csum[c]) >= need) break;
            acc += csum[c];
        }
        u32 T2 = 0;
        if (c >= 0) {
            int b;
            for (b = c * 64 + 63; b >= c * 64; --b) {
                acc += g_hist2[b];
                if ((int)acc >= need) break;
            }
            if (b < c * 64) b = c * 64;
            T2 = (u32)b;
        }
        g_thr64 = ((u64)T1 << 48) | ((u64)T2 << 32);
    }
}

// ---------------- K3b: final filter into sort buffer ----------------
__global__ void k3b_filter()
{
    int i = blockIdx.x * blockDim.x + threadIdx.x;
    int cc = g_candcnt; if (cc > CAPBIG) cc = CAPBIG;
    if (i >= cc) return;
    u64 key = g_cand[i];
    if (key >= g_thr64) {
        int pos = atomicAdd(&g_cnt2, 1);
        if (pos < SORTN) g_sort[pos] = key;
    }
}

// ---------------- sort: 4-chunk parallel bitonic on 8192, descending ----------------
__global__ void ks_presort()   // full bitonic k=2..CHUNK within each chunk
{
    __shared__ u64 s[CHUNK];
    int base = blockIdx.x * CHUNK;
    int tid = threadIdx.x;   // 512
    for (int t = tid; t < CHUNK; t += 512) s[t] = g_sort[base + t];
    __syncthreads();
    for (int k = 2; k <= CHUNK; k <<= 1) {
        for (int j = k >> 1; j > 0; j >>= 1) {
            for (int t = tid; t < CHUNK; t += 512) {
                int l = t ^ j;
                if (l > t) {
                    u64 a = s[t], b = s[l];
                    bool sw = (((base + t) & k) == 0) ? (a < b) : (a > b);
                    if (sw) { s[t] = b; s[l] = a; }
                }
            }
            __syncthreads();
        }
    }
    for (int t = tid; t < CHUNK; t += 512) g_sort[base + t] = s[t];
}

__global__ void ks_gpass(int k, int j)   // one global compare-exchange pass
{
    int t = blockIdx.x * blockDim.x + threadIdx.x;   // SORTN/2 threads
    int i = (t & (j - 1)) | ((t & ~(j - 1)) << 1);
    int l = i | j;
    u64 a = g_sort[i], b = g_sort[l];
    bool sw = ((i & k) == 0) ? (a < b) : (a > b);
    if (sw) { g_sort[i] = b; g_sort[l] = a; }
}

__global__ void ks_lmerge(int k)   // j = CHUNK/2 .. 1 within each chunk
{
    __shared__ u64 s[CHUNK];
    int base = blockIdx.x * CHUNK;
    int tid = threadIdx.x;
    for (int t = tid; t < CHUNK; t += 512) s[t] = g_sort[base + t];
    __syncthreads();
    for (int j = CHUNK >> 1; j > 0; j >>= 1) {
        for (int t = tid; t < CHUNK; t += 512) {
            int l = t ^ j;
            if (l > t) {
                u64 a = s[t], b = s[l];
                bool sw = (((base + t) & k) == 0) ? (a < b) : (a > b);
                if (sw) { s[t] = b; s[l] = a; }
            }
        }
        __syncthreads();
    }
    for (int t = tid; t < CHUNK; t += 512) g_sort[base + t] = s[t];
}

// ---------------- K4z: decode the sorted top-6000 boxes ----------------
__global__ void k4z_decode(const float* __restrict__ del,
                           const float* __restrict__ img,
                           const float* __restrict__ anchors)
{
    int t = blockIdx.x * blockDim.x + threadIdx.x;
    if (t >= PRE) return;
    u64 key = g_sort[t];
    if (key == 0ull) {
        atomicOr(&g_supp[t >> 6], 1ull << (t & 63));
        g_boxes[t] = make_float4(0.f, 0.f, 0.f, 0.f);
    } else {
        float imH1 = __fsub_rn(img[0], 1.0f);
        float imW1 = __fsub_rn(img[1], 1.0f);
        float ms   = __fmul_rn(16.0f, img[2]);
        const float4* anc = (const float4*)anchors;
        u32 idx = 0xFFFFFFFFu - (u32)(key & 0xFFFFFFFFull);
        int pix = idx / NA;
        int a   = idx - pix * NA;
        bool valid;
        g_boxes[t] = decode_box(pix, a, del, anc, imW1, imH1, ms, valid);
    }
}

// ---------------- K5: IoU bitmask matrix ----------------
__global__ void k5_mask()
{
    __shared__ float4 cb[64];
    int cB = blockIdx.x, rB = blockIdx.y;
    int t = threadIdx.x;
    int j0 = cB * 64;
    int j = j0 + t;
    cb[t] = (j < PRE) ? g_boxes[j] : make_float4(0.f, 0.f, -1.f, -1.f);
    __syncthreads();

    int i = rB * 64 + t;
    if (i >= PRE) return;

    u64 word = 0ull;
    if (j0 + 63 > i) {
        float4 bi = g_boxes[i];
        float ai = __fmul_rn(__fadd_rn(__fsub_rn(bi.z, bi.x), 1.0f),
                             __fadd_rn(__fsub_rn(bi.w, bi.y), 1.0f));
        int cmax = min(64, PRE - j0);
        for (int c = 0; c < cmax; ++c) {
            int jj = j0 + c;
            if (jj <= i) continue;
            float4 bj = cb[c];
            float ix1 = fmaxf(bi.x, bj.x);
            float iy1 = fmaxf(bi.y, bj.y);
            float ix2 = fminf(bi.z, bj.z);
            float iy2 = fminf(bi.w, bj.w);
            float iw = fmaxf(__fadd_rn(__fsub_rn(ix2, ix1), 1.0f), 0.0f);
            float ih = fmaxf(__fadd_rn(__fsub_rn(iy2, iy1), 1.0f), 0.0f);
            float inter = __fmul_rn(iw, ih);
            float aj = __fmul_rn(__fadd_rn(__fsub_rn(bj.z, bj.x), 1.0f),
                                 __fadd_rn(__fsub_rn(bj.w, bj.y), 1.0f));
            float iou = __fdiv_rn(inter, __fsub_rn(__fadd_rn(ai, aj), inter));
            if (iou > NMS_T) word |= (1ull << c);
        }
    }
    g_mask[(size_t)i * WPITCH + cB] = word;
}

// ---------------- K6: sequential NMS scan (ffs + speculative prefetch) ----------------
__global__ void k6_scan(float* __restrict__ out)
{
    int lane = threadIdx.x;
    u64 S0 = g_supp[lane];
    u64 S1 = g_supp[lane + 32];
    u64 S2 = (lane < 30) ? g_supp[lane + 64] : 0ull;

    int kept = 0;
    int pi = -1;
    u64 p0 = 0, p1 = 0, p2 = 0;

    for (int wi = 0; wi < NWORDS && kept < POST; ++wi) {
        int slot = wi >> 5, src = wi & 31;
        u64 mine = (slot == 0) ? S0 : ((slot == 1) ? S1 : S2);
        u64 w = __shfl_sync(0xFFFFFFFFu, mine, src);
        u64 alive = ~w;
        int bmax = min(64, PRE - wi * 64);
        if (bmax < 64) alive &= (1ull << bmax) - 1ull;

        while (alive && kept < POST) {
            int b = __ffsll(alive) - 1;
            alive &= alive - 1ull;
            int i = wi * 64 + b;

            u64 r0, r1, r2;
            if (pi == i) { r0 = p0; r1 = p1; r2 = p2; }
            else {
                size_t base = (size_t)i * WPITCH;
                r0 = g_mask[base + lane];
                r1 = g_mask[base + lane + 32];
                r2 = (lane < 30) ? g_mask[base + lane + 64] : 0ull;
            }

            // speculative prefetch: assume the next alive bit survives this row's OR
            if (alive) {
                int b2 = __ffsll(alive) - 1;
                int i2 = wi * 64 + b2;
                size_t base2 = (size_t)i2 * WPITCH;
                p0 = g_mask[base2 + lane];
                p1 = g_mask[base2 + lane + 32];
                p2 = (lane < 30) ? g_mask[base2 + lane + 64] : 0ull;
                pi = i2;
            } else pi = -1;

            const float* bp = (const float*)&g_boxes[i];
            if (lane < 4)       out[kept * 5 + 1 + lane] = bp[lane];
            else if (lane == 4) out[kept * 5] = 0.0f;
            kept++;

            S0 |= r0; S1 |= r1; S2 |= r2;
            u64 rm = (slot == 0) ? r0 : ((slot == 1) ? r1 : r2);
            alive &= ~__shfl_sync(0xFFFFFFFFu, rm, src);
        }
    }
    int rem = (POST - kept) * 5;
    for (int z = lane; z < rem; z += 32)
        out[kept * 5 + z] = 0.0f;
}

// ---------------- launch ----------------
extern "C" void kernel_launch(void* const* d_in, const int* in_sizes, int n_in,
                              void* d_out, int out_size)
{
    const float* probs   = (const float*)d_in[0];
    const float* del     = (const float*)d_in[1];
    const float* img     = (const float*)d_in[2];
    const float* anchors = (const float*)d_in[3];
    float* out = (float*)d_out;

    k0_zero<<<256, 256>>>();
    k1_keys<<<HWPIX / 256, 256>>>(probs, del, img, anchors);
    k2_t1<<<1, 1024>>>();
    k3_compact<<<TOT / 256, 256>>>();
    k2b_t2<<<1, 1024>>>();
    k3b_filter<<<CAPBIG / 256, 256>>>();

    ks_presort<<<NCHUNK, 512>>>();
    ks_gpass<<<SORTN / 2048, 1024>>>(4096, 2048);
    ks_lmerge<<<NCHUNK, 512>>>(4096);
    ks_gpass<<<SORTN / 2048, 1024>>>(8192, 4096);
    ks_gpass<<<SORTN / 2048, 1024>>>(8192, 2048);
    ks_lmerge<<<NCHUNK, 512>>>(8192);

    k4z_decode<<<(PRE + 255) / 256, 256>>>(del, img, anchors);
    k5_mask<<<dim3(NWORDS, NWORDS), 64>>>();
    k6_scan<<<1, 32>>>(out);
}

// round 5
// speedup vs baseline: 1.4047x; 1.0352x over previous
#include <cuda_runtime.h>
#include <cstdint>

typedef unsigned long long u64;
typedef unsigned int u32;

// ---------------- problem constants ----------------
#define H 256
#define W 256
#define NA 9
#define HWPIX 65536
#define TOT 589824
#define PRE 6000
#define POST 300
#define NMS_T 0.7f
#define NWORDS 94
#define WPITCH 96
#define CAPBIG 16384
#define SORTN 8192
#define CHUNK 2048
#define NCHUNK 4
#define NBINS 65536

// ---------------- scratch ----------------
__device__ u32 g_obs[TOT];
__device__ u32 g_hist[NBINS];
__device__ u32 g_hist2[NBINS];
__device__ int g_T1;
__device__ u32 g_above;
__device__ u64 g_thr64;
__device__ int g_candcnt;
__device__ int g_cnt2;
__device__ u64 g_cand[CAPBIG];
__device__ u64 g_sort[SORTN];
__device__ float4 g_boxes[PRE];
__device__ u64 g_supp[WPITCH];
__device__ u64 g_mask[(size_t)PRE * WPITCH];

// ---------------- box decode (explicit RN: match XLA no-fma) ----------------
__device__ __forceinline__ float4 decode_box(int pix, int a,
                                             const float* __restrict__ del,
                                             const float4* __restrict__ anc,
                                             float imW1, float imH1, float ms,
                                             bool& valid)
{
    float sx = __fmul_rn((float)(pix & (W - 1)), 16.0f);
    float sy = __fmul_rn((float)(pix >> 8), 16.0f);
    float4 A = anc[a];
    float ax1 = __fadd_rn(A.x, sx);
    float ay1 = __fadd_rn(A.y, sy);
    float ax2 = __fadd_rn(A.z, sx);
    float ay2 = __fadd_rn(A.w, sy);
    float aw  = __fadd_rn(__fsub_rn(ax2, ax1), 1.0f);
    float ah  = __fadd_rn(__fsub_rn(ay2, ay1), 1.0f);
    float acx = __fadd_rn(ax1, __fmul_rn(0.5f, aw));
    float acy = __fadd_rn(ay1, __fmul_rn(0.5f, ah));

    int base = (4 * a) * HWPIX + pix;
    float dx = del[base];
    float dy = del[base + HWPIX];
    float dw = del[base + 2 * HWPIX];
    float dh = del[base + 3 * HWPIX];
    dw = fminf(fmaxf(dw, -10.0f), 10.0f);
    dh = fminf(fmaxf(dh, -10.0f), 10.0f);

    float pcx = __fadd_rn(__fmul_rn(dx, aw), acx);
    float pcy = __fadd_rn(__fmul_rn(dy, ah), acy);
    float pw  = __fmul_rn(expf(dw), aw);
    float ph  = __fmul_rn(expf(dh), ah);

    float hx = __fmul_rn(0.5f, pw);
    float hy = __fmul_rn(0.5f, ph);
    float x1 = fminf(fmaxf(__fsub_rn(pcx, hx), 0.0f), imW1);
    float y1 = fminf(fmaxf(__fsub_rn(pcy, hy), 0.0f), imH1);
    float x2 = fminf(fmaxf(__fsub_rn(__fadd_rn(pcx, hx), 1.0f), 0.0f), imW1);
    float y2 = fminf(fmaxf(__fsub_rn(__fadd_rn(pcy, hy), 1.0f), 0.0f), imH1);

    valid = (__fadd_rn(__fsub_rn(x2, x1), 1.0f) >= ms) &&
            (__fadd_rn(__fsub_rn(y2, y1), 1.0f) >= ms);
    return make_float4(x1, y1, x2, y2);
}

// ---------------- K0: zero scratch ----------------
__global__ void k0_zero()
{
    int i = blockIdx.x * blockDim.x + threadIdx.x;
    if (i < NBINS)  { g_hist[i] = 0u; g_hist2[i] = 0u; }
    if (i < SORTN)  g_sort[i] = 0ull;
    if (i < WPITCH) g_supp[i] = 0ull;
    if (i == 0)     { g_candcnt = 0; g_cnt2 = 0; }
}

// ---------------- K1: ordered score bits + level-1 histogram ----------------
__global__ void k1_keys(const float* __restrict__ probs,
                        const float* __restrict__ del,
                        const float* __restrict__ img,
                        const float* __restrict__ anchors)
{
    int pix = blockIdx.x * blockDim.x + threadIdx.x;
    if (pix >= HWPIX) return;
    float imH1 = __fsub_rn(img[0], 1.0f);
    float imW1 = __fsub_rn(img[1], 1.0f);
    float ms   = __fmul_rn(16.0f, img[2]);
    const float4* anc = (const float4*)anchors;

#pragma unroll
    for (int a = 0; a < NA; ++a) {
        float score = probs[(NA + a) * HWPIX + pix];
        bool valid;
        (void)decode_box(pix, a, del, anc, imW1, imH1, ms, valid);
        u32 idx = (u32)(pix * NA + a);
        u32 ob = 0u;
        if (valid) {
            u32 sb = __float_as_uint(score);
            ob = (sb & 0x80000000u) ? ~sb : (sb | 0x80000000u);
            atomicAdd(&g_hist[ob >> 16], 1u);
        }
        g_obs[idx] = ob;
    }
}

// ---------------- parallel threshold search (suffix scan on coarse, smem fine) ----------------
__device__ __forceinline__ void threshold_search(const u32* __restrict__ hist,
                                                 int target, int* outBin, u32* outAbove)
{
    __shared__ u32 co[1024];
    __shared__ u32 fs[64];
    __shared__ int c_blk;
    __shared__ u32 above_c;
    int t = threadIdx.x;

    u32 s = 0;
#pragma unroll 8
    for (int b = 0; b < 64; ++b) s += hist[t * 64 + b];
    u32 cur = s;
    co[t] = cur;
    __syncthreads();
    for (int off = 1; off < 1024; off <<= 1) {
        u32 oth = (t + off < 1024) ? co[t + off] : 0u;
        __syncthreads();
        cur += oth;
        co[t] = cur;
        __syncthreads();
    }
    if (t == 0) c_blk = -1;
    __syncthreads();
    u32 nxt = (t < 1023) ? co[t + 1] : 0u;
    if (cur >= (u32)target && nxt < (u32)target) { c_blk = t; above_c = nxt; }
    __syncthreads();

    int c = c_blk;
    if (c < 0) { if (t == 0) { *outBin = 0; *outAbove = 0u; } return; }
    if (t < 64) fs[t] = hist[c * 64 + t];
    __syncthreads();
    if (t == 0) {
        u32 acc = above_c;
        int b;
        for (b = 63; b >= 0; --b) {
            acc += fs[b];
            if (acc >= (u32)target) break;
        }
        if (b < 0) b = 0;
        *outBin = c * 64 + b;
        *outAbove = acc - fs[b];
    }
}

__global__ void k2_t1()
{
    __shared__ int bin;
    __shared__ u32 above;
    threshold_search(g_hist, PRE, &bin, &above);
    __syncthreads();
    if (threadIdx.x == 0) { g_T1 = bin; g_above = above; }
}

__global__ void k2b_t2()
{
    __shared__ int bin;
    __shared__ u32 above;
    int need = PRE - (int)g_above;
    threshold_search(g_hist2, need, &bin, &above);
    __syncthreads();
    if (threadIdx.x == 0)
        g_thr64 = ((u64)(u32)g_T1 << 48) | ((u64)(u32)bin << 32);
}

// ---------------- K3: compact candidates >= T1 (vectorized, warp-aggregated) ----------------
__global__ void k3_compact()
{
    int base = (blockIdx.x * blockDim.x + threadIdx.x) * 4;
    if (base >= TOT) return;
    uint4 v = *(const uint4*)(g_obs + base);
    u32 obs[4] = { v.x, v.y, v.z, v.w };
    u32 T1 = (u32)g_T1;
    int lane = threadIdx.x & 31;

#pragma unroll
    for (int k = 0; k < 4; ++k) {
        u32 ob = obs[k];
        bool keep = (ob != 0u) && ((ob >> 16) >= T1);
        u32 m = __ballot_sync(0xFFFFFFFFu, keep);
        if (keep) {
            int rank = __popc(m & ((1u << lane) - 1));
            int leader = __ffs(m) - 1;
            int bp = 0;
            if (lane == leader) bp = atomicAdd(&g_candcnt, __popc(m));
            bp = __shfl_sync(m, bp, leader);          // mask = active keep-lanes only
            int pos = bp + rank;
            if (pos < CAPBIG)
                g_cand[pos] = ((u64)ob << 32) | (u64)(0xFFFFFFFFu - (u32)(base + k));
            if ((ob >> 16) == T1) atomicAdd(&g_hist2[ob & 0xFFFFu], 1u);
        }
    }
}

// ---------------- K3b: final filter into sort buffer ----------------
__global__ void k3b_filter()
{
    int i = blockIdx.x * blockDim.x + threadIdx.x;
    int cc = g_candcnt; if (cc > CAPBIG) cc = CAPBIG;
    if (i >= cc) return;
    u64 key = g_cand[i];
    if (key >= g_thr64) {
        int pos = atomicAdd(&g_cnt2, 1);
        if (pos < SORTN) g_sort[pos] = key;
    }
}

// ---------------- sort: 4-chunk parallel bitonic on 8192, descending ----------------
__global__ void ks_presort()
{
    __shared__ u64 s[CHUNK];
    int base = blockIdx.x * CHUNK;
    int tid = threadIdx.x;   // 512
    for (int t = tid; t < CHUNK; t += 512) s[t] = g_sort[base + t];
    __syncthreads();
    for (int k = 2; k <= CHUNK; k <<= 1) {
        for (int j = k >> 1; j > 0; j >>= 1) {
            for (int t = tid; t < CHUNK; t += 512) {
                int l = t ^ j;
                if (l > t) {
                    u64 a = s[t], b = s[l];
                    bool sw = (((base + t) & k) == 0) ? (a < b) : (a > b);
                    if (sw) { s[t] = b; s[l] = a; }
                }
            }
            __syncthreads();
        }
    }
    for (int t = tid; t < CHUNK; t += 512) g_sort[base + t] = s[t];
}

__global__ void ks_gpass(int k, int j)
{
    int t = blockIdx.x * blockDim.x + threadIdx.x;
    int i = (t & (j - 1)) | ((t & ~(j - 1)) << 1);
    int l = i | j;
    u64 a = g_sort[i], b = g_sort[l];
    bool sw = ((i & k) == 0) ? (a < b) : (a > b);
    if (sw) { g_sort[i] = b; g_sort[l] = a; }
}

__global__ void ks_lmerge(int k)
{
    __shared__ u64 s[CHUNK];
    int base = blockIdx.x * CHUNK;
    int tid = threadIdx.x;
    for (int t = tid; t < CHUNK; t += 512) s[t] = g_sort[base + t];
    __syncthreads();
    for (int j = CHUNK >> 1; j > 0; j >>= 1) {
        for (int t = tid; t < CHUNK; t += 512) {
            int l = t ^ j;
            if (l > t) {
                u64 a = s[t], b = s[l];
                bool sw = (((base + t) & k) == 0) ? (a < b) : (a > b);
                if (sw) { s[t] = b; s[l] = a; }
            }
        }
        __syncthreads();
    }
    for (int t = tid; t < CHUNK; t += 512) g_sort[base + t] = s[t];
}

// ---------------- K4z: decode the sorted top-6000 boxes ----------------
__global__ void k4z_decode(const float* __restrict__ del,
                           const float* __restrict__ img,
                           const float* __restrict__ anchors)
{
    int t = blockIdx.x * blockDim.x + threadIdx.x;
    if (t >= PRE) return;
    u64 key = g_sort[t];
    if (key == 0ull) {
        atomicOr(&g_supp[t >> 6], 1ull << (t & 63));
        g_boxes[t] = make_float4(0.f, 0.f, 0.f, 0.f);
    } else {
        float imH1 = __fsub_rn(img[0], 1.0f);
        float imW1 = __fsub_rn(img[1], 1.0f);
        float ms   = __fmul_rn(16.0f, img[2]);
        const float4* anc = (const float4*)anchors;
        u32 idx = 0xFFFFFFFFu - (u32)(key & 0xFFFFFFFFull);
        int pix = idx / NA;
        int a   = idx - pix * NA;
        bool valid;
        g_boxes[t] = decode_box(pix, a, del, anc, imW1, imH1, ms, valid);
    }
}

// ---------------- K5: IoU bitmask matrix (256-thread blocks) ----------------
__global__ void k5_mask()
{
    __shared__ float4 cb[64];
    int cB = blockIdx.x, rB = blockIdx.y;
    int t = threadIdx.x;
    int j0 = cB * 64;
    if (t < 64) {
        int j = j0 + t;
        cb[t] = (j < PRE) ? g_boxes[j] : make_float4(0.f, 0.f, -1.f, -1.f);
    }
    __syncthreads();

    int i = rB * 256 + t;
    if (i >= PRE) return;

    u64 word = 0ull;
    if (j0 + 63 > i) {
        float4 bi = g_boxes[i];
        float ai = __fmul_rn(__fadd_rn(__fsub_rn(bi.z, bi.x), 1.0f),
                             __fadd_rn(__fsub_rn(bi.w, bi.y), 1.0f));
        int cmax = min(64, PRE - j0);
        for (int c = 0; c < cmax; ++c) {
            int jj = j0 + c;
            if (jj <= i) continue;
            float4 bj = cb[c];
            float ix1 = fmaxf(bi.x, bj.x);
            float iy1 = fmaxf(bi.y, bj.y);
            float ix2 = fminf(bi.z, bj.z);
            float iy2 = fminf(bi.w, bj.w);
            float iw = fmaxf(__fadd_rn(__fsub_rn(ix2, ix1), 1.0f), 0.0f);
            float ih = fmaxf(__fadd_rn(__fsub_rn(iy2, iy1), 1.0f), 0.0f);
            float inter = __fmul_rn(iw, ih);
            float aj = __fmul_rn(__fadd_rn(__fsub_rn(bj.z, bj.x), 1.0f),
                                 __fadd_rn(__fsub_rn(bj.w, bj.y), 1.0f));
            float iou = __fdiv_rn(inter, __fsub_rn(__fadd_rn(ai, aj), inter));
            if (iou > NMS_T) word |= (1ull << c);
        }
    }
    g_mask[(size_t)i * WPITCH + cB] = word;
}

// ---------------- K6: NMS scan — batched diag preload + deferred row ORs ----------------
__global__ void k6_scan(float* __restrict__ out)
{
    int lane = threadIdx.x;
    u64 S0 = g_supp[lane];
    u64 S1 = g_supp[lane + 32];
    u64 S2 = (lane < 30) ? g_supp[lane + 64] : 0ull;

    int kept = 0;
    for (int wi = 0; wi < NWORDS && kept < POST; ++wi) {
        // preload diagonal words for this 64-wide window (independent of S)
        int r_lo = wi * 64 + lane;
        int r_hi = r_lo + 32;
        u64 d_lo = g_mask[(size_t)r_lo * WPITCH + wi];
        u64 d_hi = (r_hi < PRE) ? g_mask[(size_t)r_hi * WPITCH + wi] : 0ull;

        int slot = wi >> 5, src = wi & 31;
        u64 mine = (slot == 0) ? S0 : ((slot == 1) ? S1 : S2);
        u64 w = __shfl_sync(0xFFFFFFFFu, mine, src);
        u64 alive = ~w;
        int bmax = min(64, PRE - wi * 64);
        if (bmax < 64) alive &= (1ull << bmax) - 1ull;

        while (alive && kept < POST) {
            int b = __ffsll(alive) - 1;
            alive &= alive - 1ull;
            int i = wi * 64 + b;

            const float* bp = (const float*)&g_boxes[i];
            if (lane < 4)       out[kept * 5 + 1 + lane] = bp[lane];
            else if (lane == 4) out[kept * 5] = 0.0f;
            kept++;

            // deferred: OR full row into S (consumed at next word boundary)
            size_t base = (size_t)i * WPITCH;
            S0 |= g_mask[base + lane];
            S1 |= g_mask[base + lane + 32];
            if (lane < 30) S2 |= g_mask[base + lane + 64];

            // within-window suppression from preloaded diag words (shuffle only)
            u64 dwb = __shfl_sync(0xFFFFFFFFu, (b < 32) ? d_lo : d_hi, b & 31);
            alive &= ~dwb;
        }
    }
    int rem = (POST - kept) * 5;
    for (int z = lane; z < rem; z += 32)
        out[kept * 5 + z] = 0.0f;
}

// ---------------- launch ----------------
extern "C" void kernel_launch(void* const* d_in, const int* in_sizes, int n_in,
                              void* d_out, int out_size)
{
    const float* probs   = (const float*)d_in[0];
    const float* del     = (const float*)d_in[1];
    const float* img     = (const float*)d_in[2];
    const float* anchors = (const float*)d_in[3];
    float* out = (float*)d_out;

    k0_zero<<<256, 256>>>();
    k1_keys<<<HWPIX / 256, 256>>>(probs, del, img, anchors);
    k2_t1<<<1, 1024>>>();
    k3_compact<<<TOT / 1024, 256>>>();
    k2b_t2<<<1, 1024>>>();
    k3b_filter<<<CAPBIG / 256, 256>>>();

    ks_presort<<<NCHUNK, 512>>>();
    ks_gpass<<<SORTN / 2048, 1024>>>(4096, 2048);
    ks_lmerge<<<NCHUNK, 512>>>(4096);
    ks_gpass<<<SORTN / 2048, 1024>>>(8192, 4096);
    ks_gpass<<<SORTN / 2048, 1024>>>(8192, 2048);
    ks_lmerge<<<NCHUNK, 512>>>(8192);

    k4z_decode<<<(PRE + 255) / 256, 256>>>(del, img, anchors);
    k5_mask<<<dim3(NWORDS, 24), 256>>>();
    k6_scan<<<1, 32>>>(out);
}